// round 1
// baseline (speedup 1.0000x reference)
#include <cuda_runtime.h>
#include <math.h>

// ---------------------------------------------------------------------------
// QuantMlp: x -> reorder -> fake_quant -> fc1 -> gelu(exact) -> fake_quant -> fc2
// Shapes: M=32768 tokens, D=1152, H=4608. All fp32.
// Round-1 baseline: exact fp32 pipeline, register-blocked SGEMM (NT layout).
// ---------------------------------------------------------------------------

#define MAX_M 32768
#define MAX_D 1152
#define MAX_H 4608

// Scratch (allocation-free rule: __device__ globals)
__device__ float g_xq[(size_t)MAX_M * MAX_D];          // 151 MB: fake-quantized input
__device__ float g_h[(size_t)MAX_M * MAX_H];           // 604 MB: gelu(fc1) output
__device__ float g_scale[MAX_M];                       // per-token scale of gelu(h)

// ---------------------------------------------------------------------------
// Kernel 1: channel reorder + per-token fake-quant of x  -> g_xq
// One block per token.
// ---------------------------------------------------------------------------
__global__ void fq_input_kernel(const float* __restrict__ x,
                                const int* __restrict__ ridx,
                                float* __restrict__ xq, int D) {
    int t = blockIdx.x;
    const float* xrow = x + (size_t)t * D;
    float* orow = xq + (size_t)t * D;

    float amax = 0.0f;
    for (int d = threadIdx.x; d < D; d += blockDim.x)
        amax = fmaxf(amax, fabsf(xrow[ridx[d]]));

    __shared__ float red[32];
    #pragma unroll
    for (int o = 16; o; o >>= 1)
        amax = fmaxf(amax, __shfl_xor_sync(0xffffffffu, amax, o));
    if ((threadIdx.x & 31) == 0) red[threadIdx.x >> 5] = amax;
    __syncthreads();
    if (threadIdx.x < 32) {
        float v = (threadIdx.x < (blockDim.x + 31) / 32) ? red[threadIdx.x] : 0.0f;
        #pragma unroll
        for (int o = 16; o; o >>= 1)
            v = fmaxf(v, __shfl_xor_sync(0xffffffffu, v, o));
        if (threadIdx.x == 0) red[0] = v;
    }
    __syncthreads();
    float scale = fmaxf(red[0] / 127.0f, 1e-8f);

    for (int d = threadIdx.x; d < D; d += blockDim.x) {
        float v = xrow[ridx[d]];
        float q = rintf(v / scale);               // round-half-to-even, like jnp.round
        q = fminf(fmaxf(q, -128.0f), 127.0f);
        orow[d] = q * scale;
    }
}

// ---------------------------------------------------------------------------
// Kernel 3: per-token abs-max over g_h (length H) -> g_scale
// ---------------------------------------------------------------------------
__global__ void rowmax_kernel(const float* __restrict__ h,
                              float* __restrict__ scales, int H) {
    int t = blockIdx.x;
    const float* hrow = h + (size_t)t * H;
    float amax = 0.0f;
    for (int j = threadIdx.x; j < H; j += blockDim.x)
        amax = fmaxf(amax, fabsf(hrow[j]));

    __shared__ float red[32];
    #pragma unroll
    for (int o = 16; o; o >>= 1)
        amax = fmaxf(amax, __shfl_xor_sync(0xffffffffu, amax, o));
    if ((threadIdx.x & 31) == 0) red[threadIdx.x >> 5] = amax;
    __syncthreads();
    if (threadIdx.x < 32) {
        float v = (threadIdx.x < (blockDim.x + 31) / 32) ? red[threadIdx.x] : 0.0f;
        #pragma unroll
        for (int o = 16; o; o >>= 1)
            v = fmaxf(v, __shfl_xor_sync(0xffffffffu, v, o));
        if (threadIdx.x == 0) scales[t] = fmaxf(v / 127.0f, 1e-8f);
    }
}

// ---------------------------------------------------------------------------
// GEMM NT: C[M,N] = A[M,K] * B[N,K]^T + bias[N], optional exact GELU epilogue,
// optional fake-quant transform on A elements at load (using per-row scales).
// 128x128 tile, BK=16, 256 threads, 8x8 per-thread accumulators.
// Assumes M%128==0, N%128==0, K%16==0 (true for this problem).
// ---------------------------------------------------------------------------
template<int QUANT_A, int GELU_OUT>
__global__ __launch_bounds__(256, 2)
void gemm_nt_kernel(const float* __restrict__ A, const float* __restrict__ B,
                    const float* __restrict__ bias,
                    const float* __restrict__ scales,
                    float* __restrict__ C, int M, int N, int K) {
    const int BM = 128, BN = 128, BK = 16;
    __shared__ float As[BK][BM + 4];
    __shared__ float Bs[BK][BN + 4];

    int tid = threadIdx.x;
    int bm = blockIdx.y * BM;
    int bn = blockIdx.x * BN;

    // Tile-load mapping: each thread loads 2 float4 from A and 2 from B.
    int lr = tid >> 2;           // 0..63 (row within half-tile)
    int lk = (tid & 3) << 2;     // 0,4,8,12 (k offset)

    const float* A0 = A + (size_t)(bm + lr) * K + lk;
    const float* A1 = A + (size_t)(bm + lr + 64) * K + lk;
    const float* B0 = B + (size_t)(bn + lr) * K + lk;
    const float* B1 = B + (size_t)(bn + lr + 64) * K + lk;

    float s0 = 1.0f, s1 = 1.0f;
    if (QUANT_A) {
        s0 = scales[bm + lr];
        s1 = scales[bm + lr + 64];
    }

    int tx = tid & 15;           // column group
    int ty = tid >> 4;           // row group
    float acc[8][8];
    #pragma unroll
    for (int i = 0; i < 8; i++)
        #pragma unroll
        for (int j = 0; j < 8; j++) acc[i][j] = 0.0f;

    for (int k0 = 0; k0 < K; k0 += BK) {
        float4 a0 = *(const float4*)(A0 + k0);
        float4 a1 = *(const float4*)(A1 + k0);
        float4 b0 = *(const float4*)(B0 + k0);
        float4 b1 = *(const float4*)(B1 + k0);

        if (QUANT_A) {
            // fake-quant transform on A at load: q = clip(rint(a/s),-128,127)*s
            a0.x = fminf(fmaxf(rintf(a0.x / s0), -128.0f), 127.0f) * s0;
            a0.y = fminf(fmaxf(rintf(a0.y / s0), -128.0f), 127.0f) * s0;
            a0.z = fminf(fmaxf(rintf(a0.z / s0), -128.0f), 127.0f) * s0;
            a0.w = fminf(fmaxf(rintf(a0.w / s0), -128.0f), 127.0f) * s0;
            a1.x = fminf(fmaxf(rintf(a1.x / s1), -128.0f), 127.0f) * s1;
            a1.y = fminf(fmaxf(rintf(a1.y / s1), -128.0f), 127.0f) * s1;
            a1.z = fminf(fmaxf(rintf(a1.z / s1), -128.0f), 127.0f) * s1;
            a1.w = fminf(fmaxf(rintf(a1.w / s1), -128.0f), 127.0f) * s1;
        }

        As[lk + 0][lr] = a0.x; As[lk + 1][lr] = a0.y;
        As[lk + 2][lr] = a0.z; As[lk + 3][lr] = a0.w;
        As[lk + 0][lr + 64] = a1.x; As[lk + 1][lr + 64] = a1.y;
        As[lk + 2][lr + 64] = a1.z; As[lk + 3][lr + 64] = a1.w;

        Bs[lk + 0][lr] = b0.x; Bs[lk + 1][lr] = b0.y;
        Bs[lk + 2][lr] = b0.z; Bs[lk + 3][lr] = b0.w;
        Bs[lk + 0][lr + 64] = b1.x; Bs[lk + 1][lr + 64] = b1.y;
        Bs[lk + 2][lr + 64] = b1.z; Bs[lk + 3][lr + 64] = b1.w;

        __syncthreads();

        #pragma unroll
        for (int k = 0; k < BK; k++) {
            float a[8], b[8];
            #pragma unroll
            for (int i = 0; i < 8; i++) a[i] = As[k][ty * 8 + i];
            #pragma unroll
            for (int j = 0; j < 8; j++) b[j] = Bs[k][tx * 8 + j];
            #pragma unroll
            for (int i = 0; i < 8; i++)
                #pragma unroll
                for (int j = 0; j < 8; j++)
                    acc[i][j] += a[i] * b[j];
        }
        __syncthreads();
    }

    // Epilogue: + bias, optional exact GELU, store.
    #pragma unroll
    for (int i = 0; i < 8; i++) {
        int row = bm + ty * 8 + i;
        float* crow = C + (size_t)row * N + bn + tx * 8;
        #pragma unroll
        for (int j = 0; j < 8; j++) {
            float v = acc[i][j] + bias[bn + tx * 8 + j];
            if (GELU_OUT)
                v = 0.5f * v * (1.0f + erff(v * 0.70710678118654752f));
            crow[j] = v;
        }
    }
}

// ---------------------------------------------------------------------------
extern "C" void kernel_launch(void* const* d_in, const int* in_sizes, int n_in,
                              void* d_out, int out_size) {
    const float* x   = (const float*)d_in[0];
    const int*   idx = (const int*)d_in[1];
    const float* W1  = (const float*)d_in[2];
    const float* b1  = (const float*)d_in[3];
    const float* W2  = (const float*)d_in[4];
    const float* b2  = (const float*)d_in[5];
    float* out = (float*)d_out;

    int D = in_sizes[1];            // 1152
    int H = in_sizes[3];            // 4608
    int M = in_sizes[0] / D;        // 32768

    void *p_xq, *p_h, *p_scale;
    cudaGetSymbolAddress(&p_xq, g_xq);
    cudaGetSymbolAddress(&p_h, g_h);
    cudaGetSymbolAddress(&p_scale, g_scale);
    float* xq = (float*)p_xq;
    float* h  = (float*)p_h;
    float* sc = (float*)p_scale;

    // 1) reorder + fake-quant input
    fq_input_kernel<<<M, 256>>>(x, idx, xq, D);

    // 2) fc1 + gelu:  h = gelu(xq @ W1^T + b1)
    {
        dim3 grid(H / 128, M / 128);
        gemm_nt_kernel<0, 1><<<grid, 256>>>(xq, W1, b1, nullptr, h, M, H, D);
    }

    // 3) per-token scale of gelu output
    rowmax_kernel<<<M, 256>>>(h, sc, H);

    // 4) fc2 with fused fake-quant on A:  out = fq(h) @ W2^T + b2
    {
        dim3 grid(D / 128, M / 128);
        gemm_nt_kernel<1, 0><<<grid, 256>>>(h, W2, b2, sc, out, M, D, H);
    }
}

// round 2
// speedup vs baseline: 1.0010x; 1.0010x over previous
#include <cuda_runtime.h>
#include <math.h>

// ---------------------------------------------------------------------------
// QuantMlp: x -> reorder -> fake_quant -> fc1 -> gelu(exact) -> fake_quant -> fc2
// Shapes: M=32768 tokens, D=1152, H=4608. All fp32.
// Round-1 baseline: exact fp32 pipeline, register-blocked SGEMM (NT layout).
// ---------------------------------------------------------------------------

#define MAX_M 32768
#define MAX_D 1152
#define MAX_H 4608

// Scratch (allocation-free rule: __device__ globals)
__device__ float g_xq[(size_t)MAX_M * MAX_D];          // 151 MB: fake-quantized input
__device__ float g_h[(size_t)MAX_M * MAX_H];           // 604 MB: gelu(fc1) output
__device__ float g_scale[MAX_M];                       // per-token scale of gelu(h)

// ---------------------------------------------------------------------------
// Kernel 1: channel reorder + per-token fake-quant of x  -> g_xq
// One block per token.
// ---------------------------------------------------------------------------
__global__ void fq_input_kernel(const float* __restrict__ x,
                                const int* __restrict__ ridx,
                                float* __restrict__ xq, int D) {
    int t = blockIdx.x;
    const float* xrow = x + (size_t)t * D;
    float* orow = xq + (size_t)t * D;

    float amax = 0.0f;
    for (int d = threadIdx.x; d < D; d += blockDim.x)
        amax = fmaxf(amax, fabsf(xrow[ridx[d]]));

    __shared__ float red[32];
    #pragma unroll
    for (int o = 16; o; o >>= 1)
        amax = fmaxf(amax, __shfl_xor_sync(0xffffffffu, amax, o));
    if ((threadIdx.x & 31) == 0) red[threadIdx.x >> 5] = amax;
    __syncthreads();
    if (threadIdx.x < 32) {
        float v = (threadIdx.x < (blockDim.x + 31) / 32) ? red[threadIdx.x] : 0.0f;
        #pragma unroll
        for (int o = 16; o; o >>= 1)
            v = fmaxf(v, __shfl_xor_sync(0xffffffffu, v, o));
        if (threadIdx.x == 0) red[0] = v;
    }
    __syncthreads();
    float scale = fmaxf(red[0] / 127.0f, 1e-8f);

    for (int d = threadIdx.x; d < D; d += blockDim.x) {
        float v = xrow[ridx[d]];
        float q = rintf(v / scale);               // round-half-to-even, like jnp.round
        q = fminf(fmaxf(q, -128.0f), 127.0f);
        orow[d] = q * scale;
    }
}

// ---------------------------------------------------------------------------
// Kernel 3: per-token abs-max over g_h (length H) -> g_scale
// ---------------------------------------------------------------------------
__global__ void rowmax_kernel(const float* __restrict__ h,
                              float* __restrict__ scales, int H) {
    int t = blockIdx.x;
    const float* hrow = h + (size_t)t * H;
    float amax = 0.0f;
    for (int j = threadIdx.x; j < H; j += blockDim.x)
        amax = fmaxf(amax, fabsf(hrow[j]));

    __shared__ float red[32];
    #pragma unroll
    for (int o = 16; o; o >>= 1)
        amax = fmaxf(amax, __shfl_xor_sync(0xffffffffu, amax, o));
    if ((threadIdx.x & 31) == 0) red[threadIdx.x >> 5] = amax;
    __syncthreads();
    if (threadIdx.x < 32) {
        float v = (threadIdx.x < (blockDim.x + 31) / 32) ? red[threadIdx.x] : 0.0f;
        #pragma unroll
        for (int o = 16; o; o >>= 1)
            v = fmaxf(v, __shfl_xor_sync(0xffffffffu, v, o));
        if (threadIdx.x == 0) scales[t] = fmaxf(v / 127.0f, 1e-8f);
    }
}

// ---------------------------------------------------------------------------
// GEMM NT: C[M,N] = A[M,K] * B[N,K]^T + bias[N], optional exact GELU epilogue,
// optional fake-quant transform on A elements at load (using per-row scales).
// 128x128 tile, BK=16, 256 threads, 8x8 per-thread accumulators.
// Assumes M%128==0, N%128==0, K%16==0 (true for this problem).
// ---------------------------------------------------------------------------
template<int QUANT_A, int GELU_OUT>
__global__ __launch_bounds__(256, 2)
void gemm_nt_kernel(const float* __restrict__ A, const float* __restrict__ B,
                    const float* __restrict__ bias,
                    const float* __restrict__ scales,
                    float* __restrict__ C, int M, int N, int K) {
    const int BM = 128, BN = 128, BK = 16;
    __shared__ float As[BK][BM + 4];
    __shared__ float Bs[BK][BN + 4];

    int tid = threadIdx.x;
    int bm = blockIdx.y * BM;
    int bn = blockIdx.x * BN;

    // Tile-load mapping: each thread loads 2 float4 from A and 2 from B.
    int lr = tid >> 2;           // 0..63 (row within half-tile)
    int lk = (tid & 3) << 2;     // 0,4,8,12 (k offset)

    const float* A0 = A + (size_t)(bm + lr) * K + lk;
    const float* A1 = A + (size_t)(bm + lr + 64) * K + lk;
    const float* B0 = B + (size_t)(bn + lr) * K + lk;
    const float* B1 = B + (size_t)(bn + lr + 64) * K + lk;

    float s0 = 1.0f, s1 = 1.0f;
    if (QUANT_A) {
        s0 = scales[bm + lr];
        s1 = scales[bm + lr + 64];
    }

    int tx = tid & 15;           // column group
    int ty = tid >> 4;           // row group
    float acc[8][8];
    #pragma unroll
    for (int i = 0; i < 8; i++)
        #pragma unroll
        for (int j = 0; j < 8; j++) acc[i][j] = 0.0f;

    for (int k0 = 0; k0 < K; k0 += BK) {
        float4 a0 = *(const float4*)(A0 + k0);
        float4 a1 = *(const float4*)(A1 + k0);
        float4 b0 = *(const float4*)(B0 + k0);
        float4 b1 = *(const float4*)(B1 + k0);

        if (QUANT_A) {
            // fake-quant transform on A at load: q = clip(rint(a/s),-128,127)*s
            a0.x = fminf(fmaxf(rintf(a0.x / s0), -128.0f), 127.0f) * s0;
            a0.y = fminf(fmaxf(rintf(a0.y / s0), -128.0f), 127.0f) * s0;
            a0.z = fminf(fmaxf(rintf(a0.z / s0), -128.0f), 127.0f) * s0;
            a0.w = fminf(fmaxf(rintf(a0.w / s0), -128.0f), 127.0f) * s0;
            a1.x = fminf(fmaxf(rintf(a1.x / s1), -128.0f), 127.0f) * s1;
            a1.y = fminf(fmaxf(rintf(a1.y / s1), -128.0f), 127.0f) * s1;
            a1.z = fminf(fmaxf(rintf(a1.z / s1), -128.0f), 127.0f) * s1;
            a1.w = fminf(fmaxf(rintf(a1.w / s1), -128.0f), 127.0f) * s1;
        }

        As[lk + 0][lr] = a0.x; As[lk + 1][lr] = a0.y;
        As[lk + 2][lr] = a0.z; As[lk + 3][lr] = a0.w;
        As[lk + 0][lr + 64] = a1.x; As[lk + 1][lr + 64] = a1.y;
        As[lk + 2][lr + 64] = a1.z; As[lk + 3][lr + 64] = a1.w;

        Bs[lk + 0][lr] = b0.x; Bs[lk + 1][lr] = b0.y;
        Bs[lk + 2][lr] = b0.z; Bs[lk + 3][lr] = b0.w;
        Bs[lk + 0][lr + 64] = b1.x; Bs[lk + 1][lr + 64] = b1.y;
        Bs[lk + 2][lr + 64] = b1.z; Bs[lk + 3][lr + 64] = b1.w;

        __syncthreads();

        #pragma unroll
        for (int k = 0; k < BK; k++) {
            float a[8], b[8];
            #pragma unroll
            for (int i = 0; i < 8; i++) a[i] = As[k][ty * 8 + i];
            #pragma unroll
            for (int j = 0; j < 8; j++) b[j] = Bs[k][tx * 8 + j];
            #pragma unroll
            for (int i = 0; i < 8; i++)
                #pragma unroll
                for (int j = 0; j < 8; j++)
                    acc[i][j] += a[i] * b[j];
        }
        __syncthreads();
    }

    // Epilogue: + bias, optional exact GELU, store.
    #pragma unroll
    for (int i = 0; i < 8; i++) {
        int row = bm + ty * 8 + i;
        float* crow = C + (size_t)row * N + bn + tx * 8;
        #pragma unroll
        for (int j = 0; j < 8; j++) {
            float v = acc[i][j] + bias[bn + tx * 8 + j];
            if (GELU_OUT)
                v = 0.5f * v * (1.0f + erff(v * 0.70710678118654752f));
            crow[j] = v;
        }
    }
}

// ---------------------------------------------------------------------------
extern "C" void kernel_launch(void* const* d_in, const int* in_sizes, int n_in,
                              void* d_out, int out_size) {
    const float* x   = (const float*)d_in[0];
    const int*   idx = (const int*)d_in[1];
    const float* W1  = (const float*)d_in[2];
    const float* b1  = (const float*)d_in[3];
    const float* W2  = (const float*)d_in[4];
    const float* b2  = (const float*)d_in[5];
    float* out = (float*)d_out;

    int D = in_sizes[1];            // 1152
    int H = in_sizes[3];            // 4608
    int M = in_sizes[0] / D;        // 32768

    void *p_xq, *p_h, *p_scale;
    cudaGetSymbolAddress(&p_xq, g_xq);
    cudaGetSymbolAddress(&p_h, g_h);
    cudaGetSymbolAddress(&p_scale, g_scale);
    float* xq = (float*)p_xq;
    float* h  = (float*)p_h;
    float* sc = (float*)p_scale;

    // 1) reorder + fake-quant input
    fq_input_kernel<<<M, 256>>>(x, idx, xq, D);

    // 2) fc1 + gelu:  h = gelu(xq @ W1^T + b1)
    {
        dim3 grid(H / 128, M / 128);
        gemm_nt_kernel<0, 1><<<grid, 256>>>(xq, W1, b1, nullptr, h, M, H, D);
    }

    // 3) per-token scale of gelu output
    rowmax_kernel<<<M, 256>>>(h, sc, H);

    // 4) fc2 with fused fake-quant on A:  out = fq(h) @ W2^T + b2
    {
        dim3 grid(D / 128, M / 128);
        gemm_nt_kernel<1, 0><<<grid, 256>>>(h, W2, b2, sc, out, M, D, H);
    }
}

// round 4
// speedup vs baseline: 3.7015x; 3.6980x over previous
#include <cuda_runtime.h>
#include <cuda_fp16.h>
#include <math.h>
#include <stdint.h>

#define MM 32768
#define DD 1152
#define HH 4608

// ---- scratch (__device__ globals; no allocation allowed) ----
__device__ float    g_sx[MM];
__device__ float    g_s2[MM];
__device__ unsigned g_amax[MM];
__device__ __half   g_aq1[(size_t)MM * DD];
__device__ __half   g_aq2[(size_t)MM * HH];
__device__ float    g_h  [(size_t)MM * HH];
__device__ __half   g_w1hi[(size_t)HH * DD], g_w1lo[(size_t)HH * DD];
__device__ __half   g_w2hi[(size_t)HH * DD], g_w2lo[(size_t)HH * DD];

__device__ __forceinline__ uint32_t swz(uint32_t b) {
    // 128B-row XOR swizzle: bits[6:4] ^= row%8  (row stride = 128B)
    return b ^ (((b >> 7) & 7u) << 4);
}
__device__ __forceinline__ uint32_t smem_u32(const void* p) {
    uint32_t a;
    asm("{ .reg .u64 t; cvta.to.shared.u64 t, %1; cvt.u32.u64 %0, t; }" : "=r"(a) : "l"(p));
    return a;
}
__device__ __forceinline__ void ldm4(uint32_t* r, uint32_t addr) {
    asm volatile("ldmatrix.sync.aligned.m8n8.x4.shared.b16 {%0,%1,%2,%3}, [%4];"
        : "=r"(r[0]), "=r"(r[1]), "=r"(r[2]), "=r"(r[3]) : "r"(addr));
}
__device__ __forceinline__ void mma16816(float* d, const uint32_t* a, uint32_t b0, uint32_t b1) {
    asm volatile("mma.sync.aligned.m16n8k16.row.col.f32.f16.f16.f32 "
        "{%0,%1,%2,%3}, {%4,%5,%6,%7}, {%8,%9}, {%0,%1,%2,%3};"
        : "+f"(d[0]), "+f"(d[1]), "+f"(d[2]), "+f"(d[3])
        : "r"(a[0]), "r"(a[1]), "r"(a[2]), "r"(a[3]), "r"(b0), "r"(b1));
}
#define CP_COMMIT() asm volatile("cp.async.commit_group;" ::: "memory")
#define CP_WAIT1()  asm volatile("cp.async.wait_group 1;" ::: "memory")

__device__ __forceinline__ float gelu_exact(float v) {
    return 0.5f * v * (1.0f + erff(v * 0.70710678118654752f));
}

// ---------------------------------------------------------------------------
// Pack W[N,K] fp32 -> fp16 hi + fp16 lo (lo holds the fp32-fp16 residual;
// subnormal fp16 is fine: tensor cores honor fp16 denormal inputs).
// ---------------------------------------------------------------------------
__global__ void pack_w(const float* __restrict__ W, size_t total,
                       __half* __restrict__ hi, __half* __restrict__ lo) {
    for (size_t i = (size_t)blockIdx.x * blockDim.x + threadIdx.x; i < total;
         i += (size_t)gridDim.x * blockDim.x) {
        float w = W[i];
        __half h = __float2half_rn(w);
        hi[i] = h;
        lo[i] = __float2half_rn(w - __half2float(h));
    }
}

// ---------------------------------------------------------------------------
// Reorder + fake-quant input: q (integer) as fp16, row-major [M,D]; scale g_sx.
// ---------------------------------------------------------------------------
__global__ void fq_input(const float* __restrict__ x, const int* __restrict__ ridx) {
    int m = blockIdx.x;
    const float* xr = x + (size_t)m * DD;
    __shared__ float red[4];
    float amax = 0.f;
    for (int d = threadIdx.x; d < DD; d += 128) amax = fmaxf(amax, fabsf(xr[ridx[d]]));
    #pragma unroll
    for (int o = 16; o; o >>= 1) amax = fmaxf(amax, __shfl_xor_sync(~0u, amax, o));
    if ((threadIdx.x & 31) == 0) red[threadIdx.x >> 5] = amax;
    __syncthreads();
    amax = fmaxf(fmaxf(red[0], red[1]), fmaxf(red[2], red[3]));
    float s = fmaxf(amax / 127.0f, 1e-8f);
    if (threadIdx.x == 0) g_sx[m] = s;
    __half* orow = g_aq1 + (size_t)m * DD;
    for (int p = threadIdx.x; p < DD / 2; p += 128) {
        float q0 = fminf(fmaxf(rintf(xr[ridx[2*p]]   / s), -128.f), 127.f);
        float q1 = fminf(fmaxf(rintf(xr[ridx[2*p+1]] / s), -128.f), 127.f);
        *(__half2*)(orow + 2*p) = __floats2half2_rn(q0, q1);
    }
}

// ---------------------------------------------------------------------------
// Quantize gelu output h -> integer q in fp16 [M,H]; scale from g_amax.
// ---------------------------------------------------------------------------
__global__ void quantize_h() {
    int m = blockIdx.x;
    float s = fmaxf(__uint_as_float(g_amax[m]) / 127.0f, 1e-8f);
    if (threadIdx.x == 0) g_s2[m] = s;
    const float* hr = g_h + (size_t)m * HH;
    __half* orow = g_aq2 + (size_t)m * HH;
    for (int p = threadIdx.x; p < HH / 2; p += 256) {
        float2 v = *(const float2*)(hr + 2*p);
        float q0 = fminf(fmaxf(rintf(v.x / s), -128.f), 127.f);
        float q1 = fminf(fmaxf(rintf(v.y / s), -128.f), 127.f);
        *(__half2*)(orow + 2*p) = __floats2half2_rn(q0, q1);
    }
}

// ---------------------------------------------------------------------------
// HMMA GEMM (NT): C[M,N] = rowscale[m]*(A @ (Bhi+Blo)^T) + bias, opt. GELU+absmax.
// A fp16-int [M,K]; Bhi/Blo fp16 [N,K]. CTA tile 128x128, BK=64, 3-stage cp.async.
// 512 threads = 16 warps (4x4), warp tile 32x32. Both passes share accumulators.
// ---------------------------------------------------------------------------
template<int GELU>
__global__ void __launch_bounds__(512)
gemm_mma(const __half* __restrict__ A, const __half* __restrict__ Bh,
         const __half* __restrict__ Bl, const float* __restrict__ bias,
         const float* __restrict__ rowscale, float* __restrict__ C,
         int ldc, int K, unsigned* __restrict__ amaxU)
{
    extern __shared__ char smem[];                     // 3 stages * (A16K + Bh16K + Bl16K)
    const uint32_t sb = smem_u32(smem);
    const int tid = threadIdx.x;
    const int wid = tid >> 5, lane = tid & 31;
    const int wm = wid >> 2, wn = wid & 3;
    const int bm = blockIdx.y * 128, bn = blockIdx.x * 128;
    const int nk = K >> 6;

    float acc[2][4][4];
    #pragma unroll
    for (int i = 0; i < 2; i++)
        #pragma unroll
        for (int j = 0; j < 4; j++)
            #pragma unroll
            for (int l = 0; l < 4; l++) acc[i][j][l] = 0.f;

    auto fill = [&](int s, int k0) {
        uint32_t st = sb + (uint32_t)s * 49152u;
        #pragma unroll
        for (int i = 0; i < 6; i++) {
            int ch = tid + i * 512;
            int tile = ch >> 10, idx = ch & 1023;
            int row = idx >> 3, j = idx & 7;
            const __half* src =
                (tile == 0 ? A + (size_t)(bm + row) * K
               : tile == 1 ? Bh + (size_t)(bn + row) * K
                           : Bl + (size_t)(bn + row) * K) + k0 + j * 8;
            uint32_t dst = st + (uint32_t)tile * 16384u + swz((uint32_t)(row * 128 + j * 16));
            asm volatile("cp.async.cg.shared.global [%0], [%1], 16;" :: "r"(dst), "l"(src));
        }
    };

    fill(0, 0);  CP_COMMIT();
    if (nk > 1) fill(1, 64);
    CP_COMMIT();

    const int lr = lane & 15, lc = lane >> 4;
    const uint32_t arow0 = (uint32_t)((wm * 32 + lr) * 128);
    const uint32_t arow1 = (uint32_t)((wm * 32 + 16 + lr) * 128);
    const uint32_t brow0 = (uint32_t)((wn * 32 + lr) * 128);
    const uint32_t brow1 = (uint32_t)((wn * 32 + 16 + lr) * 128);

    for (int ks = 0; ks < nk; ks++) {
        CP_WAIT1();
        __syncthreads();
        if (ks + 2 < nk) fill((ks + 2) % 3, (ks + 2) * 64);
        CP_COMMIT();

        uint32_t st = sb + (uint32_t)(ks % 3) * 49152u;
        #pragma unroll
        for (int kk = 0; kk < 4; kk++) {
            uint32_t cb = (uint32_t)(kk * 32 + lc * 16);
            uint32_t a[2][4], bh[2][4], bl[2][4];
            ldm4(a[0],  st + swz(arow0 + cb));
            ldm4(a[1],  st + swz(arow1 + cb));
            ldm4(bh[0], st + 16384u + swz(brow0 + cb));
            ldm4(bh[1], st + 16384u + swz(brow1 + cb));
            ldm4(bl[0], st + 32768u + swz(brow0 + cb));
            ldm4(bl[1], st + 32768u + swz(brow1 + cb));
            #pragma unroll
            for (int mt = 0; mt < 2; mt++) {
                mma16816(acc[mt][0], a[mt], bh[0][0], bh[0][2]);
                mma16816(acc[mt][1], a[mt], bh[0][1], bh[0][3]);
                mma16816(acc[mt][2], a[mt], bh[1][0], bh[1][2]);
                mma16816(acc[mt][3], a[mt], bh[1][1], bh[1][3]);
                mma16816(acc[mt][0], a[mt], bl[0][0], bl[0][2]);
                mma16816(acc[mt][1], a[mt], bl[0][1], bl[0][3]);
                mma16816(acc[mt][2], a[mt], bl[1][0], bl[1][2]);
                mma16816(acc[mt][3], a[mt], bl[1][1], bl[1][3]);
            }
        }
    }

    // ---- epilogue ----
    const int q = lane >> 2, c2 = (lane & 3) * 2;
    #pragma unroll
    for (int mt = 0; mt < 2; mt++) {
        int r0 = bm + wm * 32 + mt * 16 + q;
        float rs0 = rowscale[r0], rs1 = rowscale[r0 + 8];
        float mx0 = 0.f, mx1 = 0.f;
        #pragma unroll
        for (int nt = 0; nt < 4; nt++) {
            int col = bn + wn * 32 + nt * 8 + c2;
            float2 bb = *(const float2*)(bias + col);
            float v0 = acc[mt][nt][0] * rs0 + bb.x;
            float v1 = acc[mt][nt][1] * rs0 + bb.y;
            float v2 = acc[mt][nt][2] * rs1 + bb.x;
            float v3 = acc[mt][nt][3] * rs1 + bb.y;
            if (GELU) {
                v0 = gelu_exact(v0); v1 = gelu_exact(v1);
                v2 = gelu_exact(v2); v3 = gelu_exact(v3);
                mx0 = fmaxf(mx0, fmaxf(fabsf(v0), fabsf(v1)));
                mx1 = fmaxf(mx1, fmaxf(fabsf(v2), fabsf(v3)));
            }
            float2 o0 = {v0, v1}, o1 = {v2, v3};
            *(float2*)(C + (size_t)r0 * ldc + col) = o0;
            *(float2*)(C + (size_t)(r0 + 8) * ldc + col) = o1;
        }
        if (GELU) {
            mx0 = fmaxf(mx0, __shfl_xor_sync(~0u, mx0, 1));
            mx0 = fmaxf(mx0, __shfl_xor_sync(~0u, mx0, 2));
            mx1 = fmaxf(mx1, __shfl_xor_sync(~0u, mx1, 1));
            mx1 = fmaxf(mx1, __shfl_xor_sync(~0u, mx1, 2));
            if ((lane & 3) == 0) {
                atomicMax(amaxU + r0,     __float_as_uint(mx0));
                atomicMax(amaxU + r0 + 8, __float_as_uint(mx1));
            }
        }
    }
}

// ---------------------------------------------------------------------------
extern "C" void kernel_launch(void* const* d_in, const int* in_sizes, int n_in,
                              void* d_out, int out_size) {
    const float* x   = (const float*)d_in[0];
    const int*   idx = (const int*)d_in[1];
    const float* W1  = (const float*)d_in[2];
    const float* b1  = (const float*)d_in[3];
    const float* W2  = (const float*)d_in[4];
    const float* b2  = (const float*)d_in[5];
    float* out = (float*)d_out;

    void *aq1, *aq2, *hptr, *w1h, *w1l, *w2h, *w2l, *sx, *s2, *am;
    cudaGetSymbolAddress(&aq1, g_aq1);  cudaGetSymbolAddress(&aq2, g_aq2);
    cudaGetSymbolAddress(&hptr, g_h);
    cudaGetSymbolAddress(&w1h, g_w1hi); cudaGetSymbolAddress(&w1l, g_w1lo);
    cudaGetSymbolAddress(&w2h, g_w2hi); cudaGetSymbolAddress(&w2l, g_w2lo);
    cudaGetSymbolAddress(&sx, g_sx);    cudaGetSymbolAddress(&s2, g_s2);
    cudaGetSymbolAddress(&am, g_amax);

    const int SMEM = 3 * 49152;   // 147456 B
    cudaFuncSetAttribute(gemm_mma<1>, cudaFuncAttributeMaxDynamicSharedMemorySize, SMEM);
    cudaFuncSetAttribute(gemm_mma<0>, cudaFuncAttributeMaxDynamicSharedMemorySize, SMEM);

    pack_w<<<2048, 256>>>(W1, (size_t)HH * DD, (__half*)w1h, (__half*)w1l);
    pack_w<<<2048, 256>>>(W2, (size_t)DD * HH, (__half*)w2h, (__half*)w2l);
    cudaMemsetAsync(am, 0, MM * sizeof(unsigned));
    fq_input<<<MM, 128>>>(x, idx);

    // fc1 + gelu + row absmax
    gemm_mma<1><<<dim3(HH / 128, MM / 128), 512, SMEM>>>(
        (const __half*)aq1, (const __half*)w1h, (const __half*)w1l,
        b1, (const float*)sx, (float*)hptr, HH, DD, (unsigned*)am);

    quantize_h<<<MM, 256>>>();

    // fc2
    gemm_mma<0><<<dim3(DD / 128, MM / 128), 512, SMEM>>>(
        (const __half*)aq2, (const __half*)w2h, (const __half*)w2l,
        b2, (const float*)s2, out, DD, HH, nullptr);
}

// round 5
// speedup vs baseline: 3.9227x; 1.0598x over previous
#include <cuda_runtime.h>
#include <cuda_fp16.h>
#include <math.h>
#include <stdint.h>

#define MM 32768
#define DD 1152
#define HH 4608

// ---- scratch (__device__ globals; no allocation allowed) ----
__device__ float    g_sx[MM];
__device__ float    g_s2[MM];
__device__ unsigned g_amax[MM];
__device__ __half   g_aq1[(size_t)MM * DD];
__device__ __half   g_aq2[(size_t)MM * HH];
__device__ float    g_h  [(size_t)MM * HH];
__device__ __half   g_w1hi[(size_t)HH * DD], g_w1lo[(size_t)HH * DD];
__device__ __half   g_w2hi[(size_t)HH * DD], g_w2lo[(size_t)HH * DD];

__device__ __forceinline__ uint32_t swz(uint32_t b) {
    // 128B-row XOR swizzle: bits[6:4] ^= row%8 (row stride = 128B)
    return b ^ (((b >> 7) & 7u) << 4);
}
__device__ __forceinline__ uint32_t smem_u32(const void* p) {
    uint32_t a;
    asm("{ .reg .u64 t; cvta.to.shared.u64 t, %1; cvt.u32.u64 %0, t; }" : "=r"(a) : "l"(p));
    return a;
}
__device__ __forceinline__ void ldm4(uint32_t* r, uint32_t addr) {
    asm volatile("ldmatrix.sync.aligned.m8n8.x4.shared.b16 {%0,%1,%2,%3}, [%4];"
        : "=r"(r[0]), "=r"(r[1]), "=r"(r[2]), "=r"(r[3]) : "r"(addr));
}
__device__ __forceinline__ void mma16816(float* d, const uint32_t* a, uint32_t b0, uint32_t b1) {
    asm volatile("mma.sync.aligned.m16n8k16.row.col.f32.f16.f16.f32 "
        "{%0,%1,%2,%3}, {%4,%5,%6,%7}, {%8,%9}, {%0,%1,%2,%3};"
        : "+f"(d[0]), "+f"(d[1]), "+f"(d[2]), "+f"(d[3])
        : "r"(a[0]), "r"(a[1]), "r"(a[2]), "r"(a[3]), "r"(b0), "r"(b1));
}
#define CP_COMMIT() asm volatile("cp.async.commit_group;" ::: "memory")
#define CP_WAIT2()  asm volatile("cp.async.wait_group 2;" ::: "memory")

__device__ __forceinline__ float gelu_exact(float v) {
    return 0.5f * v * (1.0f + erff(v * 0.70710678118654752f));
}

// ---------------------------------------------------------------------------
__global__ void pack_w(const float* __restrict__ W, size_t total,
                       __half* __restrict__ hi, __half* __restrict__ lo) {
    for (size_t i = (size_t)blockIdx.x * blockDim.x + threadIdx.x; i < total;
         i += (size_t)gridDim.x * blockDim.x) {
        float w = W[i];
        __half h = __float2half_rn(w);
        hi[i] = h;
        lo[i] = __float2half_rn(w - __half2float(h));
    }
}

__global__ void fq_input(const float* __restrict__ x, const int* __restrict__ ridx) {
    int m = blockIdx.x;
    const float* xr = x + (size_t)m * DD;
    __shared__ float red[4];
    float amax = 0.f;
    for (int d = threadIdx.x; d < DD; d += 128) amax = fmaxf(amax, fabsf(xr[ridx[d]]));
    #pragma unroll
    for (int o = 16; o; o >>= 1) amax = fmaxf(amax, __shfl_xor_sync(~0u, amax, o));
    if ((threadIdx.x & 31) == 0) red[threadIdx.x >> 5] = amax;
    __syncthreads();
    amax = fmaxf(fmaxf(red[0], red[1]), fmaxf(red[2], red[3]));
    float s = fmaxf(amax / 127.0f, 1e-8f);
    if (threadIdx.x == 0) g_sx[m] = s;
    __half* orow = g_aq1 + (size_t)m * DD;
    for (int p = threadIdx.x; p < DD / 2; p += 128) {
        float q0 = fminf(fmaxf(rintf(xr[ridx[2*p]]   / s), -128.f), 127.f);
        float q1 = fminf(fmaxf(rintf(xr[ridx[2*p+1]] / s), -128.f), 127.f);
        *(__half2*)(orow + 2*p) = __floats2half2_rn(q0, q1);
    }
}

__global__ void quantize_h() {
    int m = blockIdx.x;
    float s = fmaxf(__uint_as_float(g_amax[m]) / 127.0f, 1e-8f);
    if (threadIdx.x == 0) g_s2[m] = s;
    const float* hr = g_h + (size_t)m * HH;
    __half* orow = g_aq2 + (size_t)m * HH;
    for (int p = threadIdx.x; p < HH / 2; p += 256) {
        float2 v = *(const float2*)(hr + 2*p);
        float q0 = fminf(fmaxf(rintf(v.x / s), -128.f), 127.f);
        float q1 = fminf(fmaxf(rintf(v.y / s), -128.f), 127.f);
        *(__half2*)(orow + 2*p) = __floats2half2_rn(q0, q1);
    }
}

// ---------------------------------------------------------------------------
// HMMA GEMM (NT): C = rowscale[m]*(A @ (Bhi+Blo)^T) + bias, opt. GELU + absmax.
// CTA 128x128, BK=64, 4-stage cp.async, 256 threads = 8 warps, warp tile 32x64.
// All ldmatrix swizzle offsets precomputed in registers (k-loop is add-only).
// ---------------------------------------------------------------------------
template<int GELU>
__global__ void __launch_bounds__(256)
gemm_mma(const __half* __restrict__ A, const __half* __restrict__ Bh,
         const __half* __restrict__ Bl, const float* __restrict__ bias,
         const float* __restrict__ rowscale, float* __restrict__ C,
         int ldc, int K, unsigned* __restrict__ amaxU)
{
    extern __shared__ char smem[];           // 4 stages * 48KB (A16K|Bh16K|Bl16K)
    const uint32_t sb = smem_u32(smem);
    const int tid = threadIdx.x;
    const int wid = tid >> 5, lane = tid & 31;
    const int wm = wid & 3, wn = wid >> 2;            // warp grid 4 (m) x 2 (n)
    const int bm = blockIdx.y * 128, bn = blockIdx.x * 128;
    const int nk = K >> 6;

    // Precompute swizzled ldmatrix offsets (stage-relative) once.
    const int lr = lane & 15, lc = lane >> 4;
    uint32_t aoff[2][4], boff[4][4];
    #pragma unroll
    for (int mt = 0; mt < 2; mt++)
        #pragma unroll
        for (int kk = 0; kk < 4; kk++)
            aoff[mt][kk] = swz((uint32_t)((wm * 32 + mt * 16 + lr) * 128 + kk * 32 + lc * 16));
    #pragma unroll
    for (int g = 0; g < 4; g++)
        #pragma unroll
        for (int kk = 0; kk < 4; kk++)
            boff[g][kk] = 16384u + swz((uint32_t)((wn * 64 + g * 16 + lr) * 128 + kk * 32 + lc * 16));

    float acc[2][8][4];
    #pragma unroll
    for (int i = 0; i < 2; i++)
        #pragma unroll
        for (int j = 0; j < 8; j++)
            #pragma unroll
            for (int l = 0; l < 4; l++) acc[i][j][l] = 0.f;

    auto fill = [&](int s, int k0) {
        uint32_t st = sb + (uint32_t)s * 49152u;
        #pragma unroll
        for (int i = 0; i < 12; i++) {
            int ch = tid + i * 256;
            int tile = ch >> 10, idx = ch & 1023;
            int row = idx >> 3, j = idx & 7;
            const __half* src =
                (tile == 0 ? A + (size_t)(bm + row) * K
               : tile == 1 ? Bh + (size_t)(bn + row) * K
                           : Bl + (size_t)(bn + row) * K) + k0 + j * 8;
            uint32_t dst = st + (uint32_t)tile * 16384u + swz((uint32_t)(row * 128 + j * 16));
            asm volatile("cp.async.cg.shared.global [%0], [%1], 16;" :: "r"(dst), "l"(src));
        }
    };

    fill(0, 0);   CP_COMMIT();
    fill(1, 64);  CP_COMMIT();
    fill(2, 128); CP_COMMIT();

    for (int ks = 0; ks < nk; ks++) {
        CP_WAIT2();
        __syncthreads();
        if (ks + 3 < nk) fill((ks + 3) & 3, (ks + 3) * 64);
        CP_COMMIT();

        uint32_t st = sb + (uint32_t)(ks & 3) * 49152u;
        #pragma unroll
        for (int kk = 0; kk < 4; kk++) {
            uint32_t a[2][4], bh[4][4], bl[4][4];
            #pragma unroll
            for (int mt = 0; mt < 2; mt++) ldm4(a[mt], st + aoff[mt][kk]);
            #pragma unroll
            for (int g = 0; g < 4; g++) ldm4(bh[g], st + boff[g][kk]);
            #pragma unroll
            for (int g = 0; g < 4; g++) ldm4(bl[g], st + boff[g][kk] + 16384u);
            #pragma unroll
            for (int mt = 0; mt < 2; mt++) {
                #pragma unroll
                for (int g = 0; g < 4; g++) {
                    mma16816(acc[mt][2*g],   a[mt], bh[g][0], bh[g][2]);
                    mma16816(acc[mt][2*g+1], a[mt], bh[g][1], bh[g][3]);
                }
                #pragma unroll
                for (int g = 0; g < 4; g++) {
                    mma16816(acc[mt][2*g],   a[mt], bl[g][0], bl[g][2]);
                    mma16816(acc[mt][2*g+1], a[mt], bl[g][1], bl[g][3]);
                }
            }
        }
    }

    // ---- epilogue ----
    const int q = lane >> 2, c2 = (lane & 3) * 2;
    #pragma unroll
    for (int mt = 0; mt < 2; mt++) {
        int r0 = bm + wm * 32 + mt * 16 + q;
        float rs0 = rowscale[r0], rs1 = rowscale[r0 + 8];
        float mx0 = 0.f, mx1 = 0.f;
        #pragma unroll
        for (int nt = 0; nt < 8; nt++) {
            int col = bn + wn * 64 + nt * 8 + c2;
            float2 bb = *(const float2*)(bias + col);
            float v0 = acc[mt][nt][0] * rs0 + bb.x;
            float v1 = acc[mt][nt][1] * rs0 + bb.y;
            float v2 = acc[mt][nt][2] * rs1 + bb.x;
            float v3 = acc[mt][nt][3] * rs1 + bb.y;
            if (GELU) {
                v0 = gelu_exact(v0); v1 = gelu_exact(v1);
                v2 = gelu_exact(v2); v3 = gelu_exact(v3);
                mx0 = fmaxf(mx0, fmaxf(fabsf(v0), fabsf(v1)));
                mx1 = fmaxf(mx1, fmaxf(fabsf(v2), fabsf(v3)));
            }
            float2 o0 = {v0, v1}, o1 = {v2, v3};
            *(float2*)(C + (size_t)r0 * ldc + col) = o0;
            *(float2*)(C + (size_t)(r0 + 8) * ldc + col) = o1;
        }
        if (GELU) {
            mx0 = fmaxf(mx0, __shfl_xor_sync(~0u, mx0, 1));
            mx0 = fmaxf(mx0, __shfl_xor_sync(~0u, mx0, 2));
            mx1 = fmaxf(mx1, __shfl_xor_sync(~0u, mx1, 1));
            mx1 = fmaxf(mx1, __shfl_xor_sync(~0u, mx1, 2));
            if ((lane & 3) == 0) {
                atomicMax(amaxU + r0,     __float_as_uint(mx0));
                atomicMax(amaxU + r0 + 8, __float_as_uint(mx1));
            }
        }
    }
}

// ---------------------------------------------------------------------------
extern "C" void kernel_launch(void* const* d_in, const int* in_sizes, int n_in,
                              void* d_out, int out_size) {
    const float* x   = (const float*)d_in[0];
    const int*   idx = (const int*)d_in[1];
    const float* W1  = (const float*)d_in[2];
    const float* b1  = (const float*)d_in[3];
    const float* W2  = (const float*)d_in[4];
    const float* b2  = (const float*)d_in[5];
    float* out = (float*)d_out;

    void *aq1, *aq2, *hptr, *w1h, *w1l, *w2h, *w2l, *sx, *s2, *am;
    cudaGetSymbolAddress(&aq1, g_aq1);  cudaGetSymbolAddress(&aq2, g_aq2);
    cudaGetSymbolAddress(&hptr, g_h);
    cudaGetSymbolAddress(&w1h, g_w1hi); cudaGetSymbolAddress(&w1l, g_w1lo);
    cudaGetSymbolAddress(&w2h, g_w2hi); cudaGetSymbolAddress(&w2l, g_w2lo);
    cudaGetSymbolAddress(&sx, g_sx);    cudaGetSymbolAddress(&s2, g_s2);
    cudaGetSymbolAddress(&am, g_amax);

    const int SMEM = 4 * 49152;   // 196608 B
    cudaFuncSetAttribute(gemm_mma<1>, cudaFuncAttributeMaxDynamicSharedMemorySize, SMEM);
    cudaFuncSetAttribute(gemm_mma<0>, cudaFuncAttributeMaxDynamicSharedMemorySize, SMEM);

    pack_w<<<2048, 256>>>(W1, (size_t)HH * DD, (__half*)w1h, (__half*)w1l);
    pack_w<<<2048, 256>>>(W2, (size_t)DD * HH, (__half*)w2h, (__half*)w2l);
    cudaMemsetAsync(am, 0, MM * sizeof(unsigned));
    fq_input<<<MM, 128>>>(x, idx);

    // fc1 + gelu + row absmax
    gemm_mma<1><<<dim3(HH / 128, MM / 128), 256, SMEM>>>(
        (const __half*)aq1, (const __half*)w1h, (const __half*)w1l,
        b1, (const float*)sx, (float*)hptr, HH, DD, (unsigned*)am);

    quantize_h<<<MM, 256>>>();

    // fc2
    gemm_mma<0><<<dim3(DD / 128, MM / 128), 256, SMEM>>>(
        (const __half*)aq2, (const __half*)w2h, (const __half*)w2l,
        b2, (const float*)s2, out, DD, HH, nullptr);
}

// round 6
// speedup vs baseline: 4.2795x; 1.0910x over previous
#include <cuda_runtime.h>
#include <cuda_fp16.h>
#include <math.h>
#include <stdint.h>

#define MM 32768
#define DD 1152
#define HH 4608

// ---- scratch (__device__ globals; no allocation allowed) ----
__device__ float    g_sx[MM];
__device__ float    g_s2[MM];
__device__ unsigned g_amax[MM];
__device__ __half   g_aq1[(size_t)MM * DD];
__device__ __half   g_aq2[(size_t)MM * HH];
__device__ float    g_h  [(size_t)MM * HH];
__device__ __half   g_w1hi[(size_t)HH * DD], g_w1lo[(size_t)HH * DD];
__device__ __half   g_w2hi[(size_t)HH * DD], g_w2lo[(size_t)HH * DD];

__device__ __forceinline__ uint32_t swz(uint32_t b) {
    // 128B-row XOR swizzle: bits[6:4] ^= row%8 (row stride = 128B)
    return b ^ (((b >> 7) & 7u) << 4);
}
__device__ __forceinline__ uint32_t smem_u32(const void* p) {
    uint32_t a;
    asm("{ .reg .u64 t; cvta.to.shared.u64 t, %1; cvt.u32.u64 %0, t; }" : "=r"(a) : "l"(p));
    return a;
}
__device__ __forceinline__ void ldm4(uint32_t* r, uint32_t addr) {
    asm volatile("ldmatrix.sync.aligned.m8n8.x4.shared.b16 {%0,%1,%2,%3}, [%4];"
        : "=r"(r[0]), "=r"(r[1]), "=r"(r[2]), "=r"(r[3]) : "r"(addr));
}
__device__ __forceinline__ void mma16816(float* d, const uint32_t* a, uint32_t b0, uint32_t b1) {
    asm volatile("mma.sync.aligned.m16n8k16.row.col.f32.f16.f16.f32 "
        "{%0,%1,%2,%3}, {%4,%5,%6,%7}, {%8,%9}, {%0,%1,%2,%3};"
        : "+f"(d[0]), "+f"(d[1]), "+f"(d[2]), "+f"(d[3])
        : "r"(a[0]), "r"(a[1]), "r"(a[2]), "r"(a[3]), "r"(b0), "r"(b1));
}
#define CP_COMMIT() asm volatile("cp.async.commit_group;" ::: "memory")
#define CP_WAIT1()  asm volatile("cp.async.wait_group 1;" ::: "memory")

__device__ __forceinline__ float gelu_exact(float v) {
    return 0.5f * v * (1.0f + erff(v * 0.70710678118654752f));
}

// ---------------------------------------------------------------------------
__global__ void pack_w(const float* __restrict__ W, size_t total,
                       __half* __restrict__ hi, __half* __restrict__ lo) {
    for (size_t i = (size_t)blockIdx.x * blockDim.x + threadIdx.x; i < total;
         i += (size_t)gridDim.x * blockDim.x) {
        float w = W[i];
        __half h = __float2half_rn(w);
        hi[i] = h;
        lo[i] = __float2half_rn(w - __half2float(h));
    }
}

__global__ void fq_input(const float* __restrict__ x, const int* __restrict__ ridx) {
    int m = blockIdx.x;
    const float* xr = x + (size_t)m * DD;
    __shared__ float red[4];
    float amax = 0.f;
    for (int d = threadIdx.x; d < DD; d += 128) amax = fmaxf(amax, fabsf(xr[ridx[d]]));
    #pragma unroll
    for (int o = 16; o; o >>= 1) amax = fmaxf(amax, __shfl_xor_sync(~0u, amax, o));
    if ((threadIdx.x & 31) == 0) red[threadIdx.x >> 5] = amax;
    __syncthreads();
    amax = fmaxf(fmaxf(red[0], red[1]), fmaxf(red[2], red[3]));
    float s = fmaxf(amax / 127.0f, 1e-8f);
    if (threadIdx.x == 0) g_sx[m] = s;
    __half* orow = g_aq1 + (size_t)m * DD;
    for (int p = threadIdx.x; p < DD / 2; p += 128) {
        float q0 = fminf(fmaxf(rintf(xr[ridx[2*p]]   / s), -128.f), 127.f);
        float q1 = fminf(fmaxf(rintf(xr[ridx[2*p+1]] / s), -128.f), 127.f);
        *(__half2*)(orow + 2*p) = __floats2half2_rn(q0, q1);
    }
}

__global__ void quantize_h() {
    int m = blockIdx.x;
    float s = fmaxf(__uint_as_float(g_amax[m]) / 127.0f, 1e-8f);
    if (threadIdx.x == 0) g_s2[m] = s;
    const float* hr = g_h + (size_t)m * HH;
    __half* orow = g_aq2 + (size_t)m * HH;
    for (int p = threadIdx.x; p < HH / 2; p += 256) {
        float2 v = *(const float2*)(hr + 2*p);
        float q0 = fminf(fmaxf(rintf(v.x / s), -128.f), 127.f);
        float q1 = fminf(fmaxf(rintf(v.y / s), -128.f), 127.f);
        *(__half2*)(orow + 2*p) = __floats2half2_rn(q0, q1);
    }
}

// ---------------------------------------------------------------------------
// HMMA GEMM (NT): C = rowscale[m]*(A @ (Bhi+Blo)^T) + bias, opt. GELU + absmax.
// CTA 128x128, BK=64, 2-stage cp.async (96KB smem -> 2 CTAs/SM),
// 256 threads = 8 warps (4m x 2n), warp tile 32x64.
// ldmatrix addrs: addr(kk) = addr0 ^ (kk*32) thanks to XOR swizzle bit-disjointness.
// ---------------------------------------------------------------------------
template<int GELU>
__global__ void __launch_bounds__(256, 2)
gemm_mma(const __half* __restrict__ A, const __half* __restrict__ Bh,
         const __half* __restrict__ Bl, const float* __restrict__ bias,
         const float* __restrict__ rowscale, float* __restrict__ C,
         int ldc, int K, unsigned* __restrict__ amaxU)
{
    extern __shared__ char smem[];           // 2 stages * 48KB (A16K|Bh16K|Bl16K)
    const uint32_t sb = smem_u32(smem);
    const int tid = threadIdx.x;
    const int wid = tid >> 5, lane = tid & 31;
    const int wm = wid & 3, wn = wid >> 2;            // warp grid 4 (m) x 2 (n)
    const int bm = blockIdx.y * 128, bn = blockIdx.x * 128;
    const int nk = K >> 6;

    // Base swizzled ldmatrix offsets (kk=0); per-kk address = base ^ (kk*32).
    const int lr = lane & 15, lc = lane >> 4;
    uint32_t aoff[2], boff[4];
    #pragma unroll
    for (int mt = 0; mt < 2; mt++)
        aoff[mt] = swz((uint32_t)((wm * 32 + mt * 16 + lr) * 128 + lc * 16));
    #pragma unroll
    for (int g = 0; g < 4; g++)
        boff[g] = 16384u + swz((uint32_t)((wn * 64 + g * 16 + lr) * 128 + lc * 16));

    float acc[2][8][4];
    #pragma unroll
    for (int i = 0; i < 2; i++)
        #pragma unroll
        for (int j = 0; j < 8; j++)
            #pragma unroll
            for (int l = 0; l < 4; l++) acc[i][j][l] = 0.f;

    auto fill = [&](int s, int k0) {
        uint32_t st = sb + (uint32_t)s * 49152u;
        #pragma unroll
        for (int i = 0; i < 12; i++) {
            int ch = tid + i * 256;
            int tile = ch >> 10, idx = ch & 1023;
            int row = idx >> 3, j = idx & 7;
            const __half* src =
                (tile == 0 ? A + (size_t)(bm + row) * K
               : tile == 1 ? Bh + (size_t)(bn + row) * K
                           : Bl + (size_t)(bn + row) * K) + k0 + j * 8;
            uint32_t dst = st + (uint32_t)tile * 16384u + swz((uint32_t)(row * 128 + j * 16));
            asm volatile("cp.async.cg.shared.global [%0], [%1], 16;" :: "r"(dst), "l"(src));
        }
    };

    fill(0, 0);  CP_COMMIT();
    if (nk > 1) fill(1, 64);
    CP_COMMIT();

    for (int ks = 0; ks < nk; ks++) {
        CP_WAIT1();
        __syncthreads();

        uint32_t st = sb + (uint32_t)(ks & 1) * 49152u;
        #pragma unroll
        for (int kk = 0; kk < 4; kk++) {
            const uint32_t kx = (uint32_t)(kk * 32);
            uint32_t a[2][4], b[4][4];
            #pragma unroll
            for (int mt = 0; mt < 2; mt++) ldm4(a[mt], st + (aoff[mt] ^ kx));
            #pragma unroll
            for (int g = 0; g < 4; g++) ldm4(b[g], st + (boff[g] ^ kx));
            #pragma unroll
            for (int mt = 0; mt < 2; mt++)
                #pragma unroll
                for (int g = 0; g < 4; g++) {
                    mma16816(acc[mt][2*g],   a[mt], b[g][0], b[g][2]);
                    mma16816(acc[mt][2*g+1], a[mt], b[g][1], b[g][3]);
                }
            #pragma unroll
            for (int g = 0; g < 4; g++) ldm4(b[g], st + 16384u + (boff[g] ^ kx));
            #pragma unroll
            for (int mt = 0; mt < 2; mt++)
                #pragma unroll
                for (int g = 0; g < 4; g++) {
                    mma16816(acc[mt][2*g],   a[mt], b[g][0], b[g][2]);
                    mma16816(acc[mt][2*g+1], a[mt], b[g][1], b[g][3]);
                }
        }

        __syncthreads();               // all warps done reading stage (ks&1)
        if (ks + 2 < nk) fill(ks & 1, (ks + 2) * 64);
        CP_COMMIT();
    }

    // ---- epilogue ----
    const int q = lane >> 2, c2 = (lane & 3) * 2;
    #pragma unroll
    for (int mt = 0; mt < 2; mt++) {
        int r0 = bm + wm * 32 + mt * 16 + q;
        float rs0 = rowscale[r0], rs1 = rowscale[r0 + 8];
        float mx0 = 0.f, mx1 = 0.f;
        #pragma unroll
        for (int nt = 0; nt < 8; nt++) {
            int col = bn + wn * 64 + nt * 8 + c2;
            float2 bb = *(const float2*)(bias + col);
            float v0 = acc[mt][nt][0] * rs0 + bb.x;
            float v1 = acc[mt][nt][1] * rs0 + bb.y;
            float v2 = acc[mt][nt][2] * rs1 + bb.x;
            float v3 = acc[mt][nt][3] * rs1 + bb.y;
            if (GELU) {
                v0 = gelu_exact(v0); v1 = gelu_exact(v1);
                v2 = gelu_exact(v2); v3 = gelu_exact(v3);
                mx0 = fmaxf(mx0, fmaxf(fabsf(v0), fabsf(v1)));
                mx1 = fmaxf(mx1, fmaxf(fabsf(v2), fabsf(v3)));
            }
            float2 o0 = {v0, v1}, o1 = {v2, v3};
            *(float2*)(C + (size_t)r0 * ldc + col) = o0;
            *(float2*)(C + (size_t)(r0 + 8) * ldc + col) = o1;
        }
        if (GELU) {
            mx0 = fmaxf(mx0, __shfl_xor_sync(~0u, mx0, 1));
            mx0 = fmaxf(mx0, __shfl_xor_sync(~0u, mx0, 2));
            mx1 = fmaxf(mx1, __shfl_xor_sync(~0u, mx1, 1));
            mx1 = fmaxf(mx1, __shfl_xor_sync(~0u, mx1, 2));
            if ((lane & 3) == 0) {
                atomicMax(amaxU + r0,     __float_as_uint(mx0));
                atomicMax(amaxU + r0 + 8, __float_as_uint(mx1));
            }
        }
    }
}

// ---------------------------------------------------------------------------
extern "C" void kernel_launch(void* const* d_in, const int* in_sizes, int n_in,
                              void* d_out, int out_size) {
    const float* x   = (const float*)d_in[0];
    const int*   idx = (const int*)d_in[1];
    const float* W1  = (const float*)d_in[2];
    const float* b1  = (const float*)d_in[3];
    const float* W2  = (const float*)d_in[4];
    const float* b2  = (const float*)d_in[5];
    float* out = (float*)d_out;

    void *aq1, *aq2, *hptr, *w1h, *w1l, *w2h, *w2l, *sx, *s2, *am;
    cudaGetSymbolAddress(&aq1, g_aq1);  cudaGetSymbolAddress(&aq2, g_aq2);
    cudaGetSymbolAddress(&hptr, g_h);
    cudaGetSymbolAddress(&w1h, g_w1hi); cudaGetSymbolAddress(&w1l, g_w1lo);
    cudaGetSymbolAddress(&w2h, g_w2hi); cudaGetSymbolAddress(&w2l, g_w2lo);
    cudaGetSymbolAddress(&sx, g_sx);    cudaGetSymbolAddress(&s2, g_s2);
    cudaGetSymbolAddress(&am, g_amax);

    const int SMEM = 2 * 49152;   // 98304 B -> 2 CTAs/SM
    cudaFuncSetAttribute(gemm_mma<1>, cudaFuncAttributeMaxDynamicSharedMemorySize, SMEM);
    cudaFuncSetAttribute(gemm_mma<0>, cudaFuncAttributeMaxDynamicSharedMemorySize, SMEM);

    pack_w<<<2048, 256>>>(W1, (size_t)HH * DD, (__half*)w1h, (__half*)w1l);
    pack_w<<<2048, 256>>>(W2, (size_t)DD * HH, (__half*)w2h, (__half*)w2l);
    cudaMemsetAsync(am, 0, MM * sizeof(unsigned));
    fq_input<<<MM, 128>>>(x, idx);

    // fc1 + gelu + row absmax
    gemm_mma<1><<<dim3(HH / 128, MM / 128), 256, SMEM>>>(
        (const __half*)aq1, (const __half*)w1h, (const __half*)w1l,
        b1, (const float*)sx, (float*)hptr, HH, DD, (unsigned*)am);

    quantize_h<<<MM, 256>>>();

    // fc2
    gemm_mma<0><<<dim3(DD / 128, MM / 128), 256, SMEM>>>(
        (const __half*)aq2, (const __half*)w2h, (const __half*)w2l,
        b2, (const float*)s2, out, DD, HH, nullptr);
}

// round 7
// speedup vs baseline: 5.2484x; 1.2264x over previous
#include <cuda_runtime.h>
#include <cuda_fp16.h>
#include <math.h>
#include <stdint.h>

#define MM 32768
#define DD 1152
#define HH 4608

// ---- scratch (__device__ globals; no allocation allowed) ----
__device__ float    g_sx[MM];
__device__ float    g_s2[MM];
__device__ unsigned g_amax[MM];
__device__ __half   g_aq1[(size_t)MM * DD];
__device__ __half   g_aq2[(size_t)MM * HH];
__device__ float    g_h  [(size_t)MM * HH];
__device__ __half   g_w1hi[(size_t)HH * DD], g_w1lo[(size_t)HH * DD];
__device__ __half   g_w2hi[(size_t)HH * DD];

__device__ __forceinline__ uint32_t swz(uint32_t b) {
    // 128B-row XOR swizzle: bits[6:4] ^= row%8 (row stride = 128B)
    return b ^ (((b >> 7) & 7u) << 4);
}
__device__ __forceinline__ uint32_t smem_u32(const void* p) {
    uint32_t a;
    asm("{ .reg .u64 t; cvta.to.shared.u64 t, %1; cvt.u32.u64 %0, t; }" : "=r"(a) : "l"(p));
    return a;
}
__device__ __forceinline__ void ldm4(uint32_t* r, uint32_t addr) {
    asm volatile("ldmatrix.sync.aligned.m8n8.x4.shared.b16 {%0,%1,%2,%3}, [%4];"
        : "=r"(r[0]), "=r"(r[1]), "=r"(r[2]), "=r"(r[3]) : "r"(addr));
}
__device__ __forceinline__ void mma16816(float* d, const uint32_t* a, uint32_t b0, uint32_t b1) {
    asm volatile("mma.sync.aligned.m16n8k16.row.col.f32.f16.f16.f32 "
        "{%0,%1,%2,%3}, {%4,%5,%6,%7}, {%8,%9}, {%0,%1,%2,%3};"
        : "+f"(d[0]), "+f"(d[1]), "+f"(d[2]), "+f"(d[3])
        : "r"(a[0]), "r"(a[1]), "r"(a[2]), "r"(a[3]), "r"(b0), "r"(b1));
}
__device__ __forceinline__ void cpa16(uint32_t dst, const void* src) {
    asm volatile("cp.async.cg.shared.global [%0], [%1], 16;" :: "r"(dst), "l"(src));
}
#define CP_COMMIT() asm volatile("cp.async.commit_group;" ::: "memory")
#define CP_WAIT1()  asm volatile("cp.async.wait_group 1;" ::: "memory")

__device__ __forceinline__ float gelu_exact(float v) {
    return 0.5f * v * (1.0f + erff(v * 0.70710678118654752f));
}

// ---------------------------------------------------------------------------
__global__ void pack_w1(const float* __restrict__ W, size_t total,
                        __half* __restrict__ hi, __half* __restrict__ lo) {
    for (size_t i = (size_t)blockIdx.x * blockDim.x + threadIdx.x; i < total;
         i += (size_t)gridDim.x * blockDim.x) {
        float w = W[i];
        __half h = __float2half_rn(w);
        hi[i] = h;
        lo[i] = __float2half_rn(w - __half2float(h));
    }
}
__global__ void pack_w2(const float* __restrict__ W, size_t total,
                        __half* __restrict__ hi) {
    for (size_t i = (size_t)blockIdx.x * blockDim.x + threadIdx.x; i < total;
         i += (size_t)gridDim.x * blockDim.x)
        hi[i] = __float2half_rn(W[i]);
}

__global__ void fq_input(const float* __restrict__ x, const int* __restrict__ ridx) {
    int m = blockIdx.x;
    const float* xr = x + (size_t)m * DD;
    __shared__ float red[4];
    float amax = 0.f;
    for (int d = threadIdx.x; d < DD; d += 128) amax = fmaxf(amax, fabsf(xr[ridx[d]]));
    #pragma unroll
    for (int o = 16; o; o >>= 1) amax = fmaxf(amax, __shfl_xor_sync(~0u, amax, o));
    if ((threadIdx.x & 31) == 0) red[threadIdx.x >> 5] = amax;
    __syncthreads();
    amax = fmaxf(fmaxf(red[0], red[1]), fmaxf(red[2], red[3]));
    float s = fmaxf(amax / 127.0f, 1e-8f);
    if (threadIdx.x == 0) g_sx[m] = s;
    __half* orow = g_aq1 + (size_t)m * DD;
    for (int p = threadIdx.x; p < DD / 2; p += 128) {
        float q0 = fminf(fmaxf(rintf(xr[ridx[2*p]]   / s), -128.f), 127.f);
        float q1 = fminf(fmaxf(rintf(xr[ridx[2*p+1]] / s), -128.f), 127.f);
        *(__half2*)(orow + 2*p) = __floats2half2_rn(q0, q1);
    }
}

__global__ void quantize_h() {
    int m = blockIdx.x;
    float s = fmaxf(__uint_as_float(g_amax[m]) / 127.0f, 1e-8f);
    if (threadIdx.x == 0) g_s2[m] = s;
    const float* hr = g_h + (size_t)m * HH;
    __half* orow = g_aq2 + (size_t)m * HH;
    for (int p = threadIdx.x; p < HH / 2; p += 256) {
        float2 v = *(const float2*)(hr + 2*p);
        float q0 = fminf(fmaxf(rintf(v.x / s), -128.f), 127.f);
        float q1 = fminf(fmaxf(rintf(v.y / s), -128.f), 127.f);
        *(__half2*)(orow + 2*p) = __floats2half2_rn(q0, q1);
    }
}

// ---------------------------------------------------------------------------
// HMMA GEMM (NT): C = rowscale[m]*(A @ (Bhi[+Blo])^T) + bias, opt GELU+absmax.
// CTA 128x128, BK=64, 2-stage cp.async, 2 CTAs/SM, 8 warps, warp tile 32x64.
// LO=1: two-pass hi+lo weights (stage 48KB). LO=0: hi only (stage 32KB).
// ---------------------------------------------------------------------------
template<int GELU, int LO>
__global__ void __launch_bounds__(256, 2)
gemm_mma(const __half* __restrict__ A, const __half* __restrict__ Bh,
         const __half* __restrict__ Bl, const float* __restrict__ bias,
         const float* __restrict__ rowscale, float* __restrict__ C,
         int ldc, int K, unsigned* __restrict__ amaxU)
{
    constexpr uint32_t STAGE = LO ? 49152u : 32768u;
    extern __shared__ char smem[];
    const uint32_t sb = smem_u32(smem);
    const int tid = threadIdx.x;
    const int wid = tid >> 5, lane = tid & 31;
    const int wm = wid & 3, wn = wid >> 2;            // warp grid 4 (m) x 2 (n)
    const int bm = blockIdx.y * 128, bn = blockIdx.x * 128;
    const int nk = K >> 6;

    // Base swizzled ldmatrix offsets (kk=0); per-kk address = base ^ (kk*32).
    const int lr = lane & 15, lc = lane >> 4;
    uint32_t aoff[2], boff[4];
    #pragma unroll
    for (int mt = 0; mt < 2; mt++)
        aoff[mt] = swz((uint32_t)((wm * 32 + mt * 16 + lr) * 128 + lc * 16));
    #pragma unroll
    for (int g = 0; g < 4; g++)
        boff[g] = 16384u + swz((uint32_t)((wn * 64 + g * 16 + lr) * 128 + lc * 16));

    float acc[2][8][4];
    #pragma unroll
    for (int i = 0; i < 2; i++)
        #pragma unroll
        for (int j = 0; j < 8; j++)
            #pragma unroll
            for (int l = 0; l < 4; l++) acc[i][j][l] = 0.f;

    // Algebraic fill addressing: tile const per unrolled copy; j=tid&7,
    // row = tid>>3 + 32*(i&3); row+32 keeps row%8 -> swz(b+4096)=swz(b)+4096.
    const uint32_t fd0 = swz((uint32_t)((tid >> 3) * 128 + (tid & 7) * 16));
    const size_t   fs0 = (size_t)(tid >> 3) * K + (tid & 7) * 8;
    const __half* fA  = A  + (size_t)bm * K + fs0;
    const __half* fBh = Bh + (size_t)bn * K + fs0;
    const __half* fBl = LO ? (Bl + (size_t)bn * K + fs0) : (const __half*)0;
    const size_t rstep = (size_t)32 * K;

    auto fill = [&](int s, int k0) {
        uint32_t st = sb + (uint32_t)s * STAGE + fd0;
        #pragma unroll
        for (int r = 0; r < 4; r++) {
            cpa16(st + r * 4096u,            fA  + r * rstep + k0);
            cpa16(st + 16384u + r * 4096u,   fBh + r * rstep + k0);
            if (LO)
                cpa16(st + 32768u + r * 4096u, fBl + r * rstep + k0);
        }
    };

    fill(0, 0);  CP_COMMIT();
    if (nk > 1) fill(1, 64);
    CP_COMMIT();

    for (int ks = 0; ks < nk; ks++) {
        CP_WAIT1();
        __syncthreads();

        uint32_t st = sb + (uint32_t)(ks & 1) * STAGE;
        #pragma unroll
        for (int kk = 0; kk < 4; kk++) {
            const uint32_t kx = (uint32_t)(kk * 32);
            uint32_t a[2][4], b[4][4];
            #pragma unroll
            for (int mt = 0; mt < 2; mt++) ldm4(a[mt], st + (aoff[mt] ^ kx));
            #pragma unroll
            for (int g = 0; g < 4; g++) ldm4(b[g], st + (boff[g] ^ kx));
            #pragma unroll
            for (int mt = 0; mt < 2; mt++)
                #pragma unroll
                for (int g = 0; g < 4; g++) {
                    mma16816(acc[mt][2*g],   a[mt], b[g][0], b[g][2]);
                    mma16816(acc[mt][2*g+1], a[mt], b[g][1], b[g][3]);
                }
            if (LO) {
                #pragma unroll
                for (int g = 0; g < 4; g++) ldm4(b[g], st + 16384u + (boff[g] ^ kx));
                #pragma unroll
                for (int mt = 0; mt < 2; mt++)
                    #pragma unroll
                    for (int g = 0; g < 4; g++) {
                        mma16816(acc[mt][2*g],   a[mt], b[g][0], b[g][2]);
                        mma16816(acc[mt][2*g+1], a[mt], b[g][1], b[g][3]);
                    }
            }
        }

        __syncthreads();               // all warps done reading stage (ks&1)
        if (ks + 2 < nk) fill(ks & 1, (ks + 2) * 64);
        CP_COMMIT();
    }

    // ---- epilogue ----
    const int q = lane >> 2, c2 = (lane & 3) * 2;
    #pragma unroll
    for (int mt = 0; mt < 2; mt++) {
        int r0 = bm + wm * 32 + mt * 16 + q;
        float rs0 = rowscale[r0], rs1 = rowscale[r0 + 8];
        float mx0 = 0.f, mx1 = 0.f;
        #pragma unroll
        for (int nt = 0; nt < 8; nt++) {
            int col = bn + wn * 64 + nt * 8 + c2;
            float2 bb = *(const float2*)(bias + col);
            float v0 = acc[mt][nt][0] * rs0 + bb.x;
            float v1 = acc[mt][nt][1] * rs0 + bb.y;
            float v2 = acc[mt][nt][2] * rs1 + bb.x;
            float v3 = acc[mt][nt][3] * rs1 + bb.y;
            if (GELU) {
                v0 = gelu_exact(v0); v1 = gelu_exact(v1);
                v2 = gelu_exact(v2); v3 = gelu_exact(v3);
                mx0 = fmaxf(mx0, fmaxf(fabsf(v0), fabsf(v1)));
                mx1 = fmaxf(mx1, fmaxf(fabsf(v2), fabsf(v3)));
            }
            float2 o0 = {v0, v1}, o1 = {v2, v3};
            *(float2*)(C + (size_t)r0 * ldc + col) = o0;
            *(float2*)(C + (size_t)(r0 + 8) * ldc + col) = o1;
        }
        if (GELU) {
            mx0 = fmaxf(mx0, __shfl_xor_sync(~0u, mx0, 1));
            mx0 = fmaxf(mx0, __shfl_xor_sync(~0u, mx0, 2));
            mx1 = fmaxf(mx1, __shfl_xor_sync(~0u, mx1, 1));
            mx1 = fmaxf(mx1, __shfl_xor_sync(~0u, mx1, 2));
            if ((lane & 3) == 0) {
                atomicMax(amaxU + r0,     __float_as_uint(mx0));
                atomicMax(amaxU + r0 + 8, __float_as_uint(mx1));
            }
        }
    }
}

// ---------------------------------------------------------------------------
extern "C" void kernel_launch(void* const* d_in, const int* in_sizes, int n_in,
                              void* d_out, int out_size) {
    const float* x   = (const float*)d_in[0];
    const int*   idx = (const int*)d_in[1];
    const float* W1  = (const float*)d_in[2];
    const float* b1  = (const float*)d_in[3];
    const float* W2  = (const float*)d_in[4];
    const float* b2  = (const float*)d_in[5];
    float* out = (float*)d_out;

    void *aq1, *aq2, *hptr, *w1h, *w1l, *w2h, *sx, *s2, *am;
    cudaGetSymbolAddress(&aq1, g_aq1);  cudaGetSymbolAddress(&aq2, g_aq2);
    cudaGetSymbolAddress(&hptr, g_h);
    cudaGetSymbolAddress(&w1h, g_w1hi); cudaGetSymbolAddress(&w1l, g_w1lo);
    cudaGetSymbolAddress(&w2h, g_w2hi);
    cudaGetSymbolAddress(&sx, g_sx);    cudaGetSymbolAddress(&s2, g_s2);
    cudaGetSymbolAddress(&am, g_amax);

    const int SMEM1 = 2 * 49152;   // 96KB  -> 2 CTAs/SM
    const int SMEM2 = 2 * 32768;   // 64KB  -> 2 CTAs/SM
    cudaFuncSetAttribute((const void*)gemm_mma<1, 1>, cudaFuncAttributeMaxDynamicSharedMemorySize, SMEM1);
    cudaFuncSetAttribute((const void*)gemm_mma<0, 0>, cudaFuncAttributeMaxDynamicSharedMemorySize, SMEM2);

    pack_w1<<<2048, 256>>>(W1, (size_t)HH * DD, (__half*)w1h, (__half*)w1l);
    pack_w2<<<2048, 256>>>(W2, (size_t)DD * HH, (__half*)w2h);
    cudaMemsetAsync(am, 0, MM * sizeof(unsigned));
    fq_input<<<MM, 128>>>(x, idx);

    // fc1 + gelu + row absmax (two-pass hi/lo weights)
    gemm_mma<1, 1><<<dim3(HH / 128, MM / 128), 256, SMEM1>>>(
        (const __half*)aq1, (const __half*)w1h, (const __half*)w1l,
        b1, (const float*)sx, (float*)hptr, HH, DD, (unsigned*)am);

    quantize_h<<<MM, 256>>>();

    // fc2 (hi-only weights: no fq after, error not amplified)
    gemm_mma<0, 0><<<dim3(DD / 128, MM / 128), 256, SMEM2>>>(
        (const __half*)aq2, (const __half*)w2h, nullptr,
        b2, (const float*)s2, out, DD, HH, nullptr);
}